// round 2
// baseline (speedup 1.0000x reference)
#include <cuda_runtime.h>

#define B_ 8
#define C_ 256
#define N_ 1024
#define K_ 16
#define CQ_ 64
#define BK_ (B_*K_)
#define MALL 640
#define NELEM_T ((size_t)BK_*C_*N_)

// ---------------- scratch (device globals; no allocation allowed) ----------------
__device__ float g_wall[MALL*C_];                 // stacked weights [640,256]
__device__ float g_ball[MALL];                    // stacked biases
__device__ float g_xt[NELEM_T];                   // x transposed [B,K,C,N]
__device__ float g_q[(size_t)BK_*CQ_*N_];         // [B,K,CQ,N]
__device__ float g_k[(size_t)BK_*CQ_*N_];         // [B,K,CQ,N]
__device__ float g_u[NELEM_T];                    // (t_w@v_w)@x + t_w@v_b   [B,K,C,N]
__device__ float g_t1[NELEM_T];                   // t_w@x + t_b             [B,K,C,N]
__device__ float g_t[NELEM_T];                    // t = t1 - u@attn         [B,K,C,N]
__device__ float g_e[(size_t)BK_*N_*N_];          // energy / attn  [B,K,N,N]  537 MB
__device__ float g_mean[C_];
__device__ float g_rstd[C_];

// ---------------- 0: fold weights:  W2 = t_w@v_w, c0 = t_w@v_b, stack ----------------
__global__ void k_prep(const float* __restrict__ qw, const float* __restrict__ kw,
                       const float* __restrict__ vw, const float* __restrict__ vb,
                       const float* __restrict__ tw, const float* __restrict__ tb) {
    int r = blockIdx.x, c = threadIdx.x;
    if (r < 64) {
        g_wall[r*C_+c] = qw[r*C_+c];
        if (c == 0) g_ball[r] = 0.f;
    } else if (r < 128) {
        g_wall[r*C_+c] = kw[(r-64)*C_+c];
        if (c == 0) g_ball[r] = 0.f;
    } else if (r < 384) {
        int o = r - 128;
        float s = 0.f;
        for (int c2 = 0; c2 < C_; c2++) s = fmaf(tw[o*C_+c2], vw[c2*C_+c], s);
        g_wall[r*C_+c] = s;
        if (c == 0) {
            float sb = 0.f;
            for (int c2 = 0; c2 < C_; c2++) sb = fmaf(tw[o*C_+c2], vb[c2], sb);
            g_ball[r] = sb;
        }
    } else {
        int o = r - 384;
        g_wall[r*C_+c] = tw[o*C_+c];
        if (c == 0) g_ball[r] = tb[o];
    }
}

// ---------------- 1: transpose x [B,C,N,K] -> xt [B,K,C,N] ----------------
__global__ void k_xpose(const float* __restrict__ x) {
    __shared__ float s[64][17];
    int b = blockIdx.z, c = blockIdx.y, n0 = blockIdx.x * 64;
    const float* src = x + ((size_t)(b*C_+c)*N_ + n0) * K_;   // 1024 contiguous floats
    int tid = threadIdx.x;
#pragma unroll
    for (int r = 0; r < 4; r++) { int i = tid + r*256; s[i>>4][i&15] = src[i]; }
    __syncthreads();
    int nn = tid & 63, kb = tid >> 6;
#pragma unroll
    for (int r = 0; r < 4; r++) {
        int kq = kb + r*4;
        g_xt[((size_t)(b*K_+kq)*C_ + c)*N_ + n0 + nn] = s[nn][kq];
    }
}

// ---------------- GEMM microkernel helpers (64x64x16 tile, 4x4/thread) ----------------
#define FMA16(acc, a, bv)                                  \
    acc[0][0]=fmaf(a.x,bv.x,acc[0][0]); acc[0][1]=fmaf(a.x,bv.y,acc[0][1]); \
    acc[0][2]=fmaf(a.x,bv.z,acc[0][2]); acc[0][3]=fmaf(a.x,bv.w,acc[0][3]); \
    acc[1][0]=fmaf(a.y,bv.x,acc[1][0]); acc[1][1]=fmaf(a.y,bv.y,acc[1][1]); \
    acc[1][2]=fmaf(a.y,bv.z,acc[1][2]); acc[1][3]=fmaf(a.y,bv.w,acc[1][3]); \
    acc[2][0]=fmaf(a.z,bv.x,acc[2][0]); acc[2][1]=fmaf(a.z,bv.y,acc[2][1]); \
    acc[2][2]=fmaf(a.z,bv.z,acc[2][2]); acc[2][3]=fmaf(a.z,bv.w,acc[2][3]); \
    acc[3][0]=fmaf(a.w,bv.x,acc[3][0]); acc[3][1]=fmaf(a.w,bv.y,acc[3][1]); \
    acc[3][2]=fmaf(a.w,bv.z,acc[3][2]); acc[3][3]=fmaf(a.w,bv.w,acc[3][3]);

// ---------------- 2: stacked channel GEMM  out[640,1024] = Wall @ xt[bk]  ----------------
__global__ void k_stage2() {
    __shared__ float As[16][64], Bs[16][64];
    int bk = blockIdx.z;
    int m0 = blockIdx.y * 64, n0 = blockIdx.x * 64;
    const float* X = g_xt + (size_t)bk * C_ * N_;
    int tid = threadIdx.x, tx = tid & 15, ty = tid >> 4;
    int t4 = tid * 4;
    int amm = t4 >> 4, akk = t4 & 15;
    int bkk = t4 >> 6, bnn = t4 & 63;
    float acc[4][4] = {};
    for (int kc = 0; kc < C_; kc += 16) {
        float4 av = *(const float4*)&g_wall[(m0+amm)*C_ + kc + akk];
        As[akk  ][amm] = av.x; As[akk+1][amm] = av.y;
        As[akk+2][amm] = av.z; As[akk+3][amm] = av.w;
        *(float4*)&Bs[bkk][bnn] = *(const float4*)&X[(size_t)(kc+bkk)*N_ + n0 + bnn];
        __syncthreads();
#pragma unroll
        for (int kk = 0; kk < 16; kk++) {
            float4 a  = *(const float4*)&As[kk][ty*4];
            float4 bv = *(const float4*)&Bs[kk][tx*4];
            FMA16(acc, a, bv)
        }
        __syncthreads();
    }
#pragma unroll
    for (int i = 0; i < 4; i++) {
        int r = m0 + ty*4 + i;
        float bias = g_ball[r];
        float* dst;
        if      (r < 64)  dst = g_q  + ((size_t)bk*CQ_ + r      ) * N_;
        else if (r < 128) dst = g_k  + ((size_t)bk*CQ_ + (r-64) ) * N_;
        else if (r < 384) dst = g_u  + ((size_t)bk*C_  + (r-128)) * N_;
        else              dst = g_t1 + ((size_t)bk*C_  + (r-384)) * N_;
        float4 v = make_float4(acc[i][0]+bias, acc[i][1]+bias, acc[i][2]+bias, acc[i][3]+bias);
        *(float4*)&dst[n0 + tx*4] = v;
    }
}

// ---------------- 3: energy E[n,m] = sum_d Q[d,n]*K[d,m]  (TN) ----------------
__global__ void k_energy() {
    __shared__ float As[16][64], Bs[16][64];
    int bk = blockIdx.z, n0 = blockIdx.y * 64, m0 = blockIdx.x * 64;
    const float* Q  = g_q + (size_t)bk * CQ_ * N_;
    const float* Kp = g_k + (size_t)bk * CQ_ * N_;
    float* E = g_e + (size_t)bk * N_ * N_;
    int tid = threadIdx.x, tx = tid & 15, ty = tid >> 4;
    int t4 = tid * 4;
    int ldd = t4 >> 6, lnn = t4 & 63;
    float acc[4][4] = {};
    for (int dc = 0; dc < CQ_; dc += 16) {
        *(float4*)&As[ldd][lnn] = *(const float4*)&Q [(size_t)(dc+ldd)*N_ + n0 + lnn];
        *(float4*)&Bs[ldd][lnn] = *(const float4*)&Kp[(size_t)(dc+ldd)*N_ + m0 + lnn];
        __syncthreads();
#pragma unroll
        for (int kk = 0; kk < 16; kk++) {
            float4 a  = *(const float4*)&As[kk][ty*4];
            float4 bv = *(const float4*)&Bs[kk][tx*4];
            FMA16(acc, a, bv)
        }
        __syncthreads();
    }
#pragma unroll
    for (int i = 0; i < 4; i++) {
        float4 v = make_float4(acc[i][0], acc[i][1], acc[i][2], acc[i][3]);
        *(float4*)&E[(size_t)(n0+ty*4+i)*N_ + m0 + tx*4] = v;
    }
}

// ---------------- 4: softmax(m) per (b,k,n) + renorm over k, in place ----------------
__global__ void k_softmax() {
    int b = blockIdx.x >> 10, n = blockIdx.x & 1023;
    int tid = threadIdx.x, lane = tid & 31, wid = tid >> 5;
    __shared__ float wred[8][16];
    __shared__ float gmax[16], ginv[16];
    float vals[16][4];
    // pass 1: load + per-k max
#pragma unroll
    for (int k = 0; k < 16; k++) {
        const float* row = g_e + ((size_t)(b*K_+k)*N_ + n) * N_;
        float m = -1e30f;
#pragma unroll
        for (int j = 0; j < 4; j++) { vals[k][j] = row[tid + j*256]; m = fmaxf(m, vals[k][j]); }
#pragma unroll
        for (int o = 16; o; o >>= 1) m = fmaxf(m, __shfl_xor_sync(0xffffffffu, m, o));
        if (lane == 0) wred[wid][k] = m;
    }
    __syncthreads();
    if (tid < 16) {
        float m = -1e30f;
#pragma unroll
        for (int w = 0; w < 8; w++) m = fmaxf(m, wred[w][tid]);
        gmax[tid] = m;
    }
    __syncthreads();
    // pass 2: exp + per-k sum
#pragma unroll
    for (int k = 0; k < 16; k++) {
        float mk = gmax[k], s = 0.f;
#pragma unroll
        for (int j = 0; j < 4; j++) { vals[k][j] = __expf(vals[k][j] - mk); s += vals[k][j]; }
#pragma unroll
        for (int o = 16; o; o >>= 1) s += __shfl_xor_sync(0xffffffffu, s, o);
        if (lane == 0) wred[wid][k] = s;
    }
    __syncthreads();
    if (tid < 16) {
        float s = 0.f;
#pragma unroll
        for (int w = 0; w < 8; w++) s += wred[w][tid];
        ginv[tid] = 1.f / s;
    }
    __syncthreads();
    // softmax values + k-sum per m, then renormalize and store
    float asum[4] = {0.f, 0.f, 0.f, 0.f};
#pragma unroll
    for (int k = 0; k < 16; k++) {
        float inv = ginv[k];
#pragma unroll
        for (int j = 0; j < 4; j++) { vals[k][j] *= inv; asum[j] += vals[k][j]; }
    }
#pragma unroll
    for (int j = 0; j < 4; j++) asum[j] = 1.f / (1e-9f + asum[j]);
#pragma unroll
    for (int k = 0; k < 16; k++) {
        float* row = g_e + ((size_t)(b*K_+k)*N_ + n) * N_;
#pragma unroll
        for (int j = 0; j < 4; j++) row[tid + j*256] = vals[k][j] * asum[j];
    }
}

// ---------------- 5: t = t1 - U @ attn   (NN, K=1024) ----------------
__global__ void k_xr() {
    __shared__ float As[16][64], Bs[16][64];
    int bk = blockIdx.z, c0 = blockIdx.y * 64, m0 = blockIdx.x * 64;
    const float* U = g_u + (size_t)bk * C_ * N_;
    const float* A = g_e + (size_t)bk * N_ * N_;
    int tid = threadIdx.x, tx = tid & 15, ty = tid >> 4;
    int t4 = tid * 4;
    int acc_cc = t4 >> 4, ann = t4 & 15;
    int bnn = t4 >> 6, bmm = t4 & 63;
    float acc[4][4] = {};
    for (int nc = 0; nc < N_; nc += 16) {
        float4 av = *(const float4*)&U[(size_t)(c0+acc_cc)*N_ + nc + ann];
        As[ann  ][acc_cc] = av.x; As[ann+1][acc_cc] = av.y;
        As[ann+2][acc_cc] = av.z; As[ann+3][acc_cc] = av.w;
        *(float4*)&Bs[bnn][bmm] = *(const float4*)&A[(size_t)(nc+bnn)*N_ + m0 + bmm];
        __syncthreads();
#pragma unroll
        for (int kk = 0; kk < 16; kk++) {
            float4 a  = *(const float4*)&As[kk][ty*4];
            float4 bv = *(const float4*)&Bs[kk][tx*4];
            FMA16(acc, a, bv)
        }
        __syncthreads();
    }
#pragma unroll
    for (int i = 0; i < 4; i++) {
        size_t idx = ((size_t)bk*C_ + c0 + ty*4 + i) * N_ + m0 + tx*4;
        float4 t1v = *(const float4*)&g_t1[idx];
        float4 o = make_float4(t1v.x - acc[i][0], t1v.y - acc[i][1],
                               t1v.z - acc[i][2], t1v.w - acc[i][3]);
        *(float4*)&g_t[idx] = o;
    }
}

// ---------------- 6: BN statistics per channel ----------------
__global__ void k_stats() {
    int c = blockIdx.x, tid = threadIdx.x;
    __shared__ float rs[256], rs2[256];
    float s = 0.f, ss = 0.f;
    for (int bk = 0; bk < BK_; bk++) {
        const float* p = g_t + ((size_t)bk*C_ + c) * N_;
        for (int i = tid; i < N_; i += 256) { float v = p[i]; s += v; ss = fmaf(v, v, ss); }
    }
    rs[tid] = s; rs2[tid] = ss;
    __syncthreads();
    for (int o = 128; o; o >>= 1) {
        if (tid < o) { rs[tid] += rs[tid+o]; rs2[tid] += rs2[tid+o]; }
        __syncthreads();
    }
    if (tid == 0) {
        const float inv = 1.f / (float)(B_*N_*K_);
        float mean = rs[0] * inv;
        float var  = rs2[0] * inv - mean * mean;
        g_mean[c] = mean;
        g_rstd[c] = rsqrtf(var + 1e-5f);
    }
}

// ---------------- 7: out = x + relu(BN(t)) with transpose back to [B,C,N,K] ----------------
__global__ void k_final(const float* __restrict__ x, const float* __restrict__ gamma,
                        const float* __restrict__ beta, float* __restrict__ out) {
    __shared__ float s[16][65];
    int b = blockIdx.z, c = blockIdx.y, n0 = blockIdx.x * 64;
    int tid = threadIdx.x;
    float mean = g_mean[c], rstd = g_rstd[c], ga = gamma[c], be = beta[c];
    int nn = tid & 63, kb = tid >> 6;
#pragma unroll
    for (int r = 0; r < 4; r++) {
        int kq = kb + r*4;
        s[kq][nn] = g_t[((size_t)(b*K_+kq)*C_ + c)*N_ + n0 + nn];
    }
    __syncthreads();
    const float* xs = x   + ((size_t)(b*C_+c)*N_ + n0) * K_;
    float*       os = out + ((size_t)(b*C_+c)*N_ + n0) * K_;
#pragma unroll
    for (int r = 0; r < 4; r++) {
        int i = tid + r*256;
        float tv = s[i & 15][i >> 4];
        float v = fmaf((tv - mean) * rstd, ga, be);
        v = fmaxf(v, 0.f);
        os[i] = xs[i] + v;
    }
}

// ---------------- launch ----------------
extern "C" void kernel_launch(void* const* d_in, const int* in_sizes, int n_in,
                              void* d_out, int out_size) {
    const float* x     = (const float*)d_in[0];
    const float* q_w   = (const float*)d_in[1];
    const float* k_w   = (const float*)d_in[2];
    const float* v_w   = (const float*)d_in[3];
    const float* v_b   = (const float*)d_in[4];
    const float* t_w   = (const float*)d_in[5];
    const float* t_b   = (const float*)d_in[6];
    const float* gamma = (const float*)d_in[7];
    const float* beta  = (const float*)d_in[8];
    float* out = (float*)d_out;

    k_prep   <<<MALL, 256>>>(q_w, k_w, v_w, v_b, t_w, t_b);
    k_xpose  <<<dim3(N_/64, C_, B_), 256>>>(x);
    k_stage2 <<<dim3(N_/64, MALL/64, BK_), 256>>>();
    k_energy <<<dim3(N_/64, N_/64, BK_), 256>>>();
    k_softmax<<<B_*N_, 256>>>();
    k_xr     <<<dim3(N_/64, C_/64, BK_), 256>>>();
    k_stats  <<<C_, 256>>>();
    k_final  <<<dim3(N_/64, C_, B_), 256>>>(x, gamma, beta, out);
}

// round 3
// speedup vs baseline: 1.0036x; 1.0036x over previous
#include <cuda_runtime.h>

#define B_ 8
#define C_ 256
#define N_ 1024
#define K_ 16
#define CQ_ 64
#define BK_ (B_*K_)
#define MALL 640
#define NELEM_T ((size_t)BK_*C_*N_)

// ---------------- scratch (device globals; no allocation allowed) ----------------
__device__ float g_wall[MALL*C_];                 // stacked weights [640,256]
__device__ float g_ball[MALL];                    // stacked biases
__device__ float g_xt[NELEM_T];                   // x transposed [B,K,C,N]
__device__ float g_q[(size_t)BK_*CQ_*N_];         // [B,K,CQ,N]
__device__ float g_k[(size_t)BK_*CQ_*N_];         // [B,K,CQ,N]
__device__ float g_u[NELEM_T];                    // (t_w@v_w)@x + t_w@v_b   [B,K,C,N]
__device__ float g_t1[NELEM_T];                   // t_w@x + t_b             [B,K,C,N]
__device__ float g_t[NELEM_T];                    // t = t1 - u@attn         [B,K,C,N]
__device__ float g_e[(size_t)BK_*N_*N_];          // energy / attn  [B,K,N,N]  537 MB
__device__ float g_mean[C_];
__device__ float g_rstd[C_];

// ---------------- 0: fold weights:  W2 = t_w@v_w, c0 = t_w@v_b, stack ----------------
__global__ void k_prep(const float* __restrict__ qw, const float* __restrict__ kw,
                       const float* __restrict__ vw, const float* __restrict__ vb,
                       const float* __restrict__ tw, const float* __restrict__ tb) {
    int r = blockIdx.x, c = threadIdx.x;
    if (r < 64) {
        g_wall[r*C_+c] = qw[r*C_+c];
        if (c == 0) g_ball[r] = 0.f;
    } else if (r < 128) {
        g_wall[r*C_+c] = kw[(r-64)*C_+c];
        if (c == 0) g_ball[r] = 0.f;
    } else if (r < 384) {
        int o = r - 128;
        float s = 0.f;
        for (int c2 = 0; c2 < C_; c2++) s = fmaf(tw[o*C_+c2], vw[c2*C_+c], s);
        g_wall[r*C_+c] = s;
        if (c == 0) {
            float sb = 0.f;
            for (int c2 = 0; c2 < C_; c2++) sb = fmaf(tw[o*C_+c2], vb[c2], sb);
            g_ball[r] = sb;
        }
    } else {
        int o = r - 384;
        g_wall[r*C_+c] = tw[o*C_+c];
        if (c == 0) g_ball[r] = tb[o];
    }
}

// ---------------- 1: transpose x [B,C,N,K] -> xt [B,K,C,N] ----------------
__global__ void k_xpose(const float* __restrict__ x) {
    __shared__ float s[64][17];
    int b = blockIdx.z, c = blockIdx.y, n0 = blockIdx.x * 64;
    const float* src = x + ((size_t)(b*C_+c)*N_ + n0) * K_;   // 1024 contiguous floats
    int tid = threadIdx.x;
#pragma unroll
    for (int r = 0; r < 4; r++) { int i = tid + r*256; s[i>>4][i&15] = src[i]; }
    __syncthreads();
    int nn = tid & 63, kb = tid >> 6;
#pragma unroll
    for (int r = 0; r < 4; r++) {
        int kq = kb + r*4;
        g_xt[((size_t)(b*K_+kq)*C_ + c)*N_ + n0 + nn] = s[nn][kq];
    }
}

// ---------------- GEMM microkernel helpers (64x64x16 tile, 4x4/thread) ----------------
#define FMA16(acc, a, bv)                                  \
    acc[0][0]=fmaf(a.x,bv.x,acc[0][0]); acc[0][1]=fmaf(a.x,bv.y,acc[0][1]); \
    acc[0][2]=fmaf(a.x,bv.z,acc[0][2]); acc[0][3]=fmaf(a.x,bv.w,acc[0][3]); \
    acc[1][0]=fmaf(a.y,bv.x,acc[1][0]); acc[1][1]=fmaf(a.y,bv.y,acc[1][1]); \
    acc[1][2]=fmaf(a.y,bv.z,acc[1][2]); acc[1][3]=fmaf(a.y,bv.w,acc[1][3]); \
    acc[2][0]=fmaf(a.z,bv.x,acc[2][0]); acc[2][1]=fmaf(a.z,bv.y,acc[2][1]); \
    acc[2][2]=fmaf(a.z,bv.z,acc[2][2]); acc[2][3]=fmaf(a.z,bv.w,acc[2][3]); \
    acc[3][0]=fmaf(a.w,bv.x,acc[3][0]); acc[3][1]=fmaf(a.w,bv.y,acc[3][1]); \
    acc[3][2]=fmaf(a.w,bv.z,acc[3][2]); acc[3][3]=fmaf(a.w,bv.w,acc[3][3]);

// ---------------- 2: stacked channel GEMM  out[640,1024] = Wall @ xt[bk]  ----------------
__global__ void k_stage2() {
    __shared__ float As[16][64], Bs[16][64];
    int bk = blockIdx.z;
    int m0 = blockIdx.y * 64, n0 = blockIdx.x * 64;
    const float* X = g_xt + (size_t)bk * C_ * N_;
    int tid = threadIdx.x, tx = tid & 15, ty = tid >> 4;
    int t4 = tid * 4;
    int amm = t4 >> 4, akk = t4 & 15;
    int bkk = t4 >> 6, bnn = t4 & 63;
    float acc[4][4] = {};
    for (int kc = 0; kc < C_; kc += 16) {
        float4 av = *(const float4*)&g_wall[(m0+amm)*C_ + kc + akk];
        As[akk  ][amm] = av.x; As[akk+1][amm] = av.y;
        As[akk+2][amm] = av.z; As[akk+3][amm] = av.w;
        *(float4*)&Bs[bkk][bnn] = *(const float4*)&X[(size_t)(kc+bkk)*N_ + n0 + bnn];
        __syncthreads();
#pragma unroll
        for (int kk = 0; kk < 16; kk++) {
            float4 a  = *(const float4*)&As[kk][ty*4];
            float4 bv = *(const float4*)&Bs[kk][tx*4];
            FMA16(acc, a, bv)
        }
        __syncthreads();
    }
#pragma unroll
    for (int i = 0; i < 4; i++) {
        int r = m0 + ty*4 + i;
        float bias = g_ball[r];
        float* dst;
        if      (r < 64)  dst = g_q  + ((size_t)bk*CQ_ + r      ) * N_;
        else if (r < 128) dst = g_k  + ((size_t)bk*CQ_ + (r-64) ) * N_;
        else if (r < 384) dst = g_u  + ((size_t)bk*C_  + (r-128)) * N_;
        else              dst = g_t1 + ((size_t)bk*C_  + (r-384)) * N_;
        float4 v = make_float4(acc[i][0]+bias, acc[i][1]+bias, acc[i][2]+bias, acc[i][3]+bias);
        *(float4*)&dst[n0 + tx*4] = v;
    }
}

// ---------------- 3: energy E[n,m] = sum_d Q[d,n]*K[d,m]  (TN) ----------------
__global__ void k_energy() {
    __shared__ float As[16][64], Bs[16][64];
    int bk = blockIdx.z, n0 = blockIdx.y * 64, m0 = blockIdx.x * 64;
    const float* Q  = g_q + (size_t)bk * CQ_ * N_;
    const float* Kp = g_k + (size_t)bk * CQ_ * N_;
    float* E = g_e + (size_t)bk * N_ * N_;
    int tid = threadIdx.x, tx = tid & 15, ty = tid >> 4;
    int t4 = tid * 4;
    int ldd = t4 >> 6, lnn = t4 & 63;
    float acc[4][4] = {};
    for (int dc = 0; dc < CQ_; dc += 16) {
        *(float4*)&As[ldd][lnn] = *(const float4*)&Q [(size_t)(dc+ldd)*N_ + n0 + lnn];
        *(float4*)&Bs[ldd][lnn] = *(const float4*)&Kp[(size_t)(dc+ldd)*N_ + m0 + lnn];
        __syncthreads();
#pragma unroll
        for (int kk = 0; kk < 16; kk++) {
            float4 a  = *(const float4*)&As[kk][ty*4];
            float4 bv = *(const float4*)&Bs[kk][tx*4];
            FMA16(acc, a, bv)
        }
        __syncthreads();
    }
#pragma unroll
    for (int i = 0; i < 4; i++) {
        float4 v = make_float4(acc[i][0], acc[i][1], acc[i][2], acc[i][3]);
        *(float4*)&E[(size_t)(n0+ty*4+i)*N_ + m0 + tx*4] = v;
    }
}

// ---------------- 4: softmax(m) per (b,k,n) + renorm over k, in place ----------------
__global__ void k_softmax() {
    int b = blockIdx.x >> 10, n = blockIdx.x & 1023;
    int tid = threadIdx.x, lane = tid & 31, wid = tid >> 5;
    __shared__ float wred[8][16];
    __shared__ float gmax[16], ginv[16];
    float vals[16][4];
    // pass 1: load + per-k max
#pragma unroll
    for (int k = 0; k < 16; k++) {
        const float* row = g_e + ((size_t)(b*K_+k)*N_ + n) * N_;
        float m = -1e30f;
#pragma unroll
        for (int j = 0; j < 4; j++) { vals[k][j] = row[tid + j*256]; m = fmaxf(m, vals[k][j]); }
#pragma unroll
        for (int o = 16; o; o >>= 1) m = fmaxf(m, __shfl_xor_sync(0xffffffffu, m, o));
        if (lane == 0) wred[wid][k] = m;
    }
    __syncthreads();
    if (tid < 16) {
        float m = -1e30f;
#pragma unroll
        for (int w = 0; w < 8; w++) m = fmaxf(m, wred[w][tid]);
        gmax[tid] = m;
    }
    __syncthreads();
    // pass 2: exp + per-k sum
#pragma unroll
    for (int k = 0; k < 16; k++) {
        float mk = gmax[k], s = 0.f;
#pragma unroll
        for (int j = 0; j < 4; j++) { vals[k][j] = __expf(vals[k][j] - mk); s += vals[k][j]; }
#pragma unroll
        for (int o = 16; o; o >>= 1) s += __shfl_xor_sync(0xffffffffu, s, o);
        if (lane == 0) wred[wid][k] = s;
    }
    __syncthreads();
    if (tid < 16) {
        float s = 0.f;
#pragma unroll
        for (int w = 0; w < 8; w++) s += wred[w][tid];
        ginv[tid] = 1.f / s;
    }
    __syncthreads();
    // softmax values + k-sum per m, then renormalize and store
    float asum[4] = {0.f, 0.f, 0.f, 0.f};
#pragma unroll
    for (int k = 0; k < 16; k++) {
        float inv = ginv[k];
#pragma unroll
        for (int j = 0; j < 4; j++) { vals[k][j] *= inv; asum[j] += vals[k][j]; }
    }
#pragma unroll
    for (int j = 0; j < 4; j++) asum[j] = 1.f / (1e-9f + asum[j]);
#pragma unroll
    for (int k = 0; k < 16; k++) {
        float* row = g_e + ((size_t)(b*K_+k)*N_ + n) * N_;
#pragma unroll
        for (int j = 0; j < 4; j++) row[tid + j*256] = vals[k][j] * asum[j];
    }
}

// ---------------- 5: t = t1 - U @ attn   (NN, K=1024) ----------------
__global__ void k_xr() {
    __shared__ float As[16][64], Bs[16][64];
    int bk = blockIdx.z, c0 = blockIdx.y * 64, m0 = blockIdx.x * 64;
    const float* U = g_u + (size_t)bk * C_ * N_;
    const float* A = g_e + (size_t)bk * N_ * N_;
    int tid = threadIdx.x, tx = tid & 15, ty = tid >> 4;
    int t4 = tid * 4;
    int acc_cc = t4 >> 4, ann = t4 & 15;
    int bnn = t4 >> 6, bmm = t4 & 63;
    float acc[4][4] = {};
    for (int nc = 0; nc < N_; nc += 16) {
        float4 av = *(const float4*)&U[(size_t)(c0+acc_cc)*N_ + nc + ann];
        As[ann  ][acc_cc] = av.x; As[ann+1][acc_cc] = av.y;
        As[ann+2][acc_cc] = av.z; As[ann+3][acc_cc] = av.w;
        *(float4*)&Bs[bnn][bmm] = *(const float4*)&A[(size_t)(nc+bnn)*N_ + m0 + bmm];
        __syncthreads();
#pragma unroll
        for (int kk = 0; kk < 16; kk++) {
            float4 a  = *(const float4*)&As[kk][ty*4];
            float4 bv = *(const float4*)&Bs[kk][tx*4];
            FMA16(acc, a, bv)
        }
        __syncthreads();
    }
#pragma unroll
    for (int i = 0; i < 4; i++) {
        size_t idx = ((size_t)bk*C_ + c0 + ty*4 + i) * N_ + m0 + tx*4;
        float4 t1v = *(const float4*)&g_t1[idx];
        float4 o = make_float4(t1v.x - acc[i][0], t1v.y - acc[i][1],
                               t1v.z - acc[i][2], t1v.w - acc[i][3]);
        *(float4*)&g_t[idx] = o;
    }
}

// ---------------- 6: BN statistics per channel ----------------
__global__ void k_stats() {
    int c = blockIdx.x, tid = threadIdx.x;
    __shared__ float rs[256], rs2[256];
    float s = 0.f, ss = 0.f;
    for (int bk = 0; bk < BK_; bk++) {
        const float* p = g_t + ((size_t)bk*C_ + c) * N_;
        for (int i = tid; i < N_; i += 256) { float v = p[i]; s += v; ss = fmaf(v, v, ss); }
    }
    rs[tid] = s; rs2[tid] = ss;
    __syncthreads();
    for (int o = 128; o; o >>= 1) {
        if (tid < o) { rs[tid] += rs[tid+o]; rs2[tid] += rs2[tid+o]; }
        __syncthreads();
    }
    if (tid == 0) {
        const float inv = 1.f / (float)(B_*N_*K_);
        float mean = rs[0] * inv;
        float var  = rs2[0] * inv - mean * mean;
        g_mean[c] = mean;
        g_rstd[c] = rsqrtf(var + 1e-5f);
    }
}

// ---------------- 7: out = x + relu(BN(t)) with transpose back to [B,C,N,K] ----------------
__global__ void k_final(const float* __restrict__ x, const float* __restrict__ gamma,
                        const float* __restrict__ beta, float* __restrict__ out) {
    __shared__ float s[16][65];
    int b = blockIdx.z, c = blockIdx.y, n0 = blockIdx.x * 64;
    int tid = threadIdx.x;
    float mean = g_mean[c], rstd = g_rstd[c], ga = gamma[c], be = beta[c];
    int nn = tid & 63, kb = tid >> 6;
#pragma unroll
    for (int r = 0; r < 4; r++) {
        int kq = kb + r*4;
        s[kq][nn] = g_t[((size_t)(b*K_+kq)*C_ + c)*N_ + n0 + nn];
    }
    __syncthreads();
    const float* xs = x   + ((size_t)(b*C_+c)*N_ + n0) * K_;
    float*       os = out + ((size_t)(b*C_+c)*N_ + n0) * K_;
#pragma unroll
    for (int r = 0; r < 4; r++) {
        int i = tid + r*256;
        float tv = s[i & 15][i >> 4];
        float v = fmaf((tv - mean) * rstd, ga, be);
        v = fmaxf(v, 0.f);
        os[i] = xs[i] + v;
    }
}

// ---------------- launch ----------------
extern "C" void kernel_launch(void* const* d_in, const int* in_sizes, int n_in,
                              void* d_out, int out_size) {
    const float* x     = (const float*)d_in[0];
    const float* q_w   = (const float*)d_in[1];
    const float* k_w   = (const float*)d_in[2];
    const float* v_w   = (const float*)d_in[3];
    const float* v_b   = (const float*)d_in[4];
    const float* t_w   = (const float*)d_in[5];
    const float* t_b   = (const float*)d_in[6];
    const float* gamma = (const float*)d_in[7];
    const float* beta  = (const float*)d_in[8];
    float* out = (float*)d_out;

    k_prep   <<<MALL, 256>>>(q_w, k_w, v_w, v_b, t_w, t_b);
    k_xpose  <<<dim3(N_/64, C_, B_), 256>>>(x);
    k_stage2 <<<dim3(N_/64, MALL/64, BK_), 256>>>();
    k_energy <<<dim3(N_/64, N_/64, BK_), 256>>>();
    k_softmax<<<B_*N_, 256>>>();
    k_xr     <<<dim3(N_/64, C_/64, BK_), 256>>>();
    k_stats  <<<C_, 256>>>();
    k_final  <<<dim3(N_/64, C_, B_), 256>>>(x, gamma, beta, out);
}